// round 4
// baseline (speedup 1.0000x reference)
#include <cuda_runtime.h>
#include <cuda_bf16.h>

#define B 4
#define L 512
#define D 128
#define TILE_I 8
#define JCH 128

// scratch for q and k projections (allocation-free rule -> __device__ globals)
__device__ float g_q[B * L * D];
__device__ float g_k[B * L * D];

// ---------------------------------------------------------------------------
// Kernel 1: q = x @ Wq^T + bq ; k = x @ Wk^T + bk
// grid = B*L blocks, 128 threads; thread e computes q[row,e], k[row,e].
// Wq/Wk rows are contiguous; they are only 64KB each -> fully L2-resident.
// ---------------------------------------------------------------------------
__global__ __launch_bounds__(128) void qk_kernel(
    const float* __restrict__ x,
    const float* __restrict__ Wq, const float* __restrict__ bq,
    const float* __restrict__ Wk, const float* __restrict__ bk)
{
    const int row = blockIdx.x;          // b*L + l
    const int e   = threadIdx.x;         // 0..127

    __shared__ float xs[D];
    xs[e] = x[row * D + e];
    __syncthreads();

    const float4* wq4 = reinterpret_cast<const float4*>(Wq + e * D);
    const float4* wk4 = reinterpret_cast<const float4*>(Wk + e * D);

    float aq = 0.f, ak = 0.f;
#pragma unroll
    for (int d4 = 0; d4 < D / 4; ++d4) {
        float4 a = wq4[d4];
        float4 c = wk4[d4];
        float x0 = xs[4 * d4 + 0], x1 = xs[4 * d4 + 1];
        float x2 = xs[4 * d4 + 2], x3 = xs[4 * d4 + 3];
        aq = fmaf(a.x, x0, aq); aq = fmaf(a.y, x1, aq);
        aq = fmaf(a.z, x2, aq); aq = fmaf(a.w, x3, aq);
        ak = fmaf(c.x, x0, ak); ak = fmaf(c.y, x1, ak);
        ak = fmaf(c.z, x2, ak); ak = fmaf(c.w, x3, ak);
    }
    g_q[row * D + e] = aq + bq[e];
    g_k[row * D + e] = ak + bk[e];
}

// ---------------------------------------------------------------------------
// Kernel 2: scores[i,j] = sum_d w[d]*tanh(q[i,d]+k[j,d]); softmax_j; out = p@x
// One block per (b, 8 consecutive i). 128 threads; thread t owns j = chunk+t.
// k chunk staged in smem with row pad 129 (conflict-free per-thread row read).
// bw dropped (softmax shift-invariant); mask is a faithful no-op.
// ---------------------------------------------------------------------------
// dynamic smem layout (floats):
//   q_s   [TILE_I*D]      = 1024
//   k_s   [JCH*129]       = 16512
//   w_s   [D]             = 128
//   sc    [TILE_I*L]      = 4096
//   red   [32]
//   s_inv [TILE_I]
#define SMEM_FLOATS (TILE_I*D + JCH*129 + D + TILE_I*L + 32 + TILE_I)
#define SMEM_BYTES  (SMEM_FLOATS * (int)sizeof(float))

__global__ __launch_bounds__(128) void attn_kernel(
    const float* __restrict__ x,
    const float* __restrict__ w,
    float* __restrict__ out)
{
    extern __shared__ float smem[];
    float* q_s   = smem;                       // 1024
    float* k_s   = q_s + TILE_I * D;           // 16512
    float* w_s   = k_s + JCH * 129;            // 128
    float* sc    = w_s + D;                    // 4096
    float* red   = sc + TILE_I * L;            // 32
    float* s_inv = red + 32;                   // 8

    const int b   = blockIdx.x >> 6;           // / (L/TILE_I)
    const int i0  = (blockIdx.x & 63) * TILE_I;
    const int tid = threadIdx.x;

    // load q tile + w
#pragma unroll
    for (int idx = tid; idx < TILE_I * D; idx += 128) {
        q_s[idx] = g_q[(b * L + i0 + (idx >> 7)) * D + (idx & (D - 1))];
    }
    w_s[tid] = w[tid];
    __syncthreads();

    // ---- main loop: 4 chunks of 128 j ----
    for (int jc = 0; jc < L / JCH; ++jc) {
        __syncthreads();   // protect k_s reuse across chunks
        // stage k chunk (coalesced float4 loads, scalar stores into padded rows)
        for (int idx = tid; idx < JCH * D / 4; idx += 128) {
            float4 v = reinterpret_cast<const float4*>(g_k)[(b * L + jc * JCH) * (D / 4) + idx];
            int jj = idx >> 5;           // idx*4 / 128
            int dd = (idx & 31) * 4;
            float* kp = &k_s[jj * 129 + dd];
            kp[0] = v.x; kp[1] = v.y; kp[2] = v.z; kp[3] = v.w;
        }
        __syncthreads();

        float acc[TILE_I];
#pragma unroll
        for (int i = 0; i < TILE_I; ++i) acc[i] = 0.f;

        const float* krow = &k_s[tid * 129];
#pragma unroll 2
        for (int d = 0; d < D; ++d) {
            float kv = krow[d];
            float wd = w_s[d];
#pragma unroll
            for (int i = 0; i < TILE_I; ++i) {
                float t = q_s[i * D + d] + kv;
                float th;
                asm("tanh.approx.f32 %0, %1;" : "=f"(th) : "f"(t));
                acc[i] = fmaf(wd, th, acc[i]);
            }
        }
#pragma unroll
        for (int i = 0; i < TILE_I; ++i) sc[i * L + jc * JCH + tid] = acc[i];
    }
    __syncthreads();

    // ---- softmax per i-row: in-place exp, keep 1/sum ----
    for (int i = 0; i < TILE_I; ++i) {
        float m = -1e30f;
        for (int jj = tid; jj < L; jj += 128) m = fmaxf(m, sc[i * L + jj]);
#pragma unroll
        for (int o = 16; o; o >>= 1) m = fmaxf(m, __shfl_xor_sync(0xffffffffu, m, o));
        if ((tid & 31) == 0) red[tid >> 5] = m;
        __syncthreads();
        m = fmaxf(fmaxf(red[0], red[1]), fmaxf(red[2], red[3]));
        __syncthreads();

        float s = 0.f;
        for (int jj = tid; jj < L; jj += 128) {
            float e = __expf(sc[i * L + jj] - m);
            sc[i * L + jj] = e;
            s += e;
        }
#pragma unroll
        for (int o = 16; o; o >>= 1) s += __shfl_xor_sync(0xffffffffu, s, o);
        if ((tid & 31) == 0) red[tid >> 5] = s;
        __syncthreads();
        if (tid == 0) s_inv[i] = 1.0f / (red[0] + red[1] + red[2] + red[3]);
        __syncthreads();
    }

    // ---- out[i, d=tid] = (1/sum) * sum_j e[i,j] * x[b,j,d] ----
    float o[TILE_I];
#pragma unroll
    for (int i = 0; i < TILE_I; ++i) o[i] = 0.f;

    const float* xb = x + b * L * D;
#pragma unroll 4
    for (int j = 0; j < L; ++j) {
        float xv = xb[j * D + tid];
#pragma unroll
        for (int i = 0; i < TILE_I; ++i) {
            o[i] = fmaf(sc[i * L + j], xv, o[i]);
        }
    }
#pragma unroll
    for (int i = 0; i < TILE_I; ++i) {
        out[(b * L + i0 + i) * D + tid] = o[i] * s_inv[i];
    }
}

// ---------------------------------------------------------------------------
extern "C" void kernel_launch(void* const* d_in, const int* in_sizes, int n_in,
                              void* d_out, int out_size)
{
    const float* x  = (const float*)d_in[0];
    // d_in[1] = mask (bool, faithfully unused by reference)
    const float* Wq = (const float*)d_in[2];
    const float* bq = (const float*)d_in[3];
    const float* Wk = (const float*)d_in[4];
    const float* bk = (const float*)d_in[5];
    const float* w  = (const float*)d_in[6];
    // d_in[7] = bw: constant shift before softmax -> no effect on output
    float* out = (float*)d_out;

    cudaFuncSetAttribute(attn_kernel, cudaFuncAttributeMaxDynamicSharedMemorySize,
                         SMEM_BYTES);

    qk_kernel<<<B * L, 128>>>(x, Wq, bq, Wk, bk);
    attn_kernel<<<B * (L / TILE_I), 128, SMEM_BYTES>>>(x, w, out);
}

// round 7
// speedup vs baseline: 1.9253x; 1.9253x over previous
#include <cuda_runtime.h>
#include <cuda_bf16.h>

#define B 4
#define L 512
#define D 128
#define TILE_I 8
#define JCH 128
#define THREADS_A 256

// scratch for q and k projections (allocation-free rule -> __device__ globals)
__device__ float g_q[B * L * D];
__device__ float g_k[B * L * D];

// ---------------------------------------------------------------------------
// Kernel 1: q = x @ Wq^T + bq ; k = x @ Wk^T + bk
// grid = B*L/8 blocks, 128 threads; thread e computes q[r,e],k[r,e] for 8 rows.
// Weight rows loaded ONCE per CTA (float4) and reused across 8 x-rows ->
// L2 weight traffic drops 8x vs row-per-CTA version.
// ---------------------------------------------------------------------------
__global__ __launch_bounds__(128) void qk_kernel(
    const float* __restrict__ x,
    const float* __restrict__ Wq, const float* __restrict__ bq,
    const float* __restrict__ Wk, const float* __restrict__ bk)
{
    const int r0 = blockIdx.x * 8;       // first row (b*L + l)
    const int e  = threadIdx.x;          // 0..127 output feature

    __shared__ float xs[8 * D];
    for (int idx = e; idx < 8 * D; idx += 128) xs[idx] = x[r0 * D + idx];
    __syncthreads();

    const float4* wq4 = reinterpret_cast<const float4*>(Wq + e * D);
    const float4* wk4 = reinterpret_cast<const float4*>(Wk + e * D);
    const float4* xs4 = reinterpret_cast<const float4*>(xs);

    float aq[8], ak[8];
#pragma unroll
    for (int r = 0; r < 8; ++r) { aq[r] = 0.f; ak[r] = 0.f; }

#pragma unroll 4
    for (int d4 = 0; d4 < D / 4; ++d4) {
        float4 a = wq4[d4];
        float4 c = wk4[d4];
#pragma unroll
        for (int r = 0; r < 8; ++r) {
            float4 xv = xs4[r * (D / 4) + d4];
            aq[r] = fmaf(a.x, xv.x, aq[r]); aq[r] = fmaf(a.y, xv.y, aq[r]);
            aq[r] = fmaf(a.z, xv.z, aq[r]); aq[r] = fmaf(a.w, xv.w, aq[r]);
            ak[r] = fmaf(c.x, xv.x, ak[r]); ak[r] = fmaf(c.y, xv.y, ak[r]);
            ak[r] = fmaf(c.z, xv.z, ak[r]); ak[r] = fmaf(c.w, xv.w, ak[r]);
        }
    }
    const float bqe = bq[e], bke = bk[e];
#pragma unroll
    for (int r = 0; r < 8; ++r) {
        g_q[(r0 + r) * D + e] = aq[r] + bqe;
        g_k[(r0 + r) * D + e] = ak[r] + bke;
    }
}

// ---------------------------------------------------------------------------
// Kernel 2: 256 threads, d-split into two groups of 128 threads.
// group g (=tid>>7) computes partial scores over d in [64g, 64g+64) for its
// j lane (=tid&127); partials summed during softmax. Per-warp softmax (warp w
// owns row i=w). Epilogue split over j-halves, combined in smem.
// bw dropped (softmax shift-invariant); mask is a faithful no-op.
// ---------------------------------------------------------------------------
// smem (floats): q_s[1024] k_s[128*129] w_s[128] sc[2*TILE_I*L] s_inv[8]
#define SMEM_FLOATS (TILE_I*D + JCH*129 + D + 2*TILE_I*L + TILE_I)
#define SMEM_BYTES  (SMEM_FLOATS * (int)sizeof(float))

__global__ __launch_bounds__(THREADS_A) void attn_kernel(
    const float* __restrict__ x,
    const float* __restrict__ w,
    float* __restrict__ out)
{
    extern __shared__ float smem[];
    float* q_s   = smem;                        // 1024
    float* k_s   = q_s + TILE_I * D;            // 16512 (pad 129)
    float* w_s   = k_s + JCH * 129;             // 128
    float* scA   = w_s + D;                     // 4096 (group0 partial, then exp)
    float* scB   = scA + TILE_I * L;            // 4096 (group1 partial)
    float* s_inv = scB + TILE_I * L;            // 8

    const int b   = blockIdx.x >> 6;
    const int i0  = (blockIdx.x & 63) * TILE_I;
    const int tid = threadIdx.x;
    const int g   = tid >> 7;                   // d-group 0/1
    const int jl  = tid & 127;                  // j lane

    // load q tile + w
    for (int idx = tid; idx < TILE_I * D; idx += THREADS_A)
        q_s[idx] = g_q[(b * L + i0) * D + idx];
    if (tid < D) w_s[tid] = w[tid];
    __syncthreads();

    float* scg = (g == 0) ? scA : scB;
    const int d0 = g * 64;

    // ---- main loop: 4 chunks of 128 j ----
    for (int jc = 0; jc < L / JCH; ++jc) {
        __syncthreads();   // k_s reuse across chunks
        // stage k chunk: coalesced scalar loads, conflict-free stores
        // (bank = (jj*129 + dd) % 32 = (jj + lane) % 32 -> all distinct)
        {
            const float* kg = g_k + (b * L + jc * JCH) * D;
            for (int idx = tid; idx < JCH * D; idx += THREADS_A) {
                int jj = idx >> 7, dd = idx & 127;
                k_s[jj * 129 + dd] = kg[idx];
            }
        }
        __syncthreads();

        float acc[TILE_I];
#pragma unroll
        for (int i = 0; i < TILE_I; ++i) acc[i] = 0.f;

        const float* krow = &k_s[jl * 129];
#pragma unroll 2
        for (int dz = 0; dz < 64; ++dz) {
            const int d = d0 + dz;
            float kv = krow[d];
            float wd = w_s[d];
#pragma unroll
            for (int i = 0; i < TILE_I; ++i) {
                float t = q_s[i * D + d] + kv;
                float th;
                asm("tanh.approx.f32 %0, %1;" : "=f"(th) : "f"(t));
                acc[i] = fmaf(wd, th, acc[i]);
            }
        }
#pragma unroll
        for (int i = 0; i < TILE_I; ++i) scg[i * L + jc * JCH + jl] = acc[i];
    }
    __syncthreads();

    // ---- per-warp softmax: warp wi owns row i=wi (8 warps, 8 rows) ----
    {
        const int wi   = tid >> 5;      // 0..7
        const int lane = tid & 31;
        float m = -1e30f;
        for (int jj = lane; jj < L; jj += 32)
            m = fmaxf(m, scA[wi * L + jj] + scB[wi * L + jj]);
#pragma unroll
        for (int o = 16; o; o >>= 1) m = fmaxf(m, __shfl_xor_sync(0xffffffffu, m, o));
        float s = 0.f;
        for (int jj = lane; jj < L; jj += 32) {
            float e = __expf(scA[wi * L + jj] + scB[wi * L + jj] - m);
            scA[wi * L + jj] = e;
            s += e;
        }
#pragma unroll
        for (int o = 16; o; o >>= 1) s += __shfl_xor_sync(0xffffffffu, s, o);
        if (lane == 0) s_inv[wi] = 1.0f / s;
    }
    __syncthreads();

    // ---- epilogue: group g sums its 256-j half; combine via smem ----
    float o[TILE_I];
#pragma unroll
    for (int i = 0; i < TILE_I; ++i) o[i] = 0.f;

    const float* xb = x + b * L * D;
    const int j0 = g * 256;
#pragma unroll 4
    for (int j = j0; j < j0 + 256; ++j) {
        float xv = xb[j * D + jl];
#pragma unroll
        for (int i = 0; i < TILE_I; ++i)
            o[i] = fmaf(scA[i * L + j], xv, o[i]);
    }

    float* op = k_s;   // reuse k_s region: [TILE_I][128]
    if (g == 1) {
#pragma unroll
        for (int i = 0; i < TILE_I; ++i) op[i * 128 + jl] = o[i];
    }
    __syncthreads();
    if (g == 0) {
#pragma unroll
        for (int i = 0; i < TILE_I; ++i)
            out[(b * L + i0 + i) * D + jl] = (o[i] + op[i * 128 + jl]) * s_inv[i];
    }
}

// ---------------------------------------------------------------------------
extern "C" void kernel_launch(void* const* d_in, const int* in_sizes, int n_in,
                              void* d_out, int out_size)
{
    const float* x  = (const float*)d_in[0];
    // d_in[1] = mask (bool, faithfully unused by reference)
    const float* Wq = (const float*)d_in[2];
    const float* bq = (const float*)d_in[3];
    const float* Wk = (const float*)d_in[4];
    const float* bk = (const float*)d_in[5];
    const float* w  = (const float*)d_in[6];
    // d_in[7] = bw: constant shift before softmax -> no effect on output
    float* out = (float*)d_out;

    cudaFuncSetAttribute(attn_kernel, cudaFuncAttributeMaxDynamicSharedMemorySize,
                         SMEM_BYTES);

    qk_kernel<<<B * L / 8, 128>>>(x, Wq, bq, Wk, bk);
    attn_kernel<<<B * (L / TILE_I), THREADS_A, SMEM_BYTES>>>(x, w, out);
}

// round 15
// speedup vs baseline: 2.1574x; 1.1206x over previous
#include <cuda_runtime.h>
#include <cuda_bf16.h>

#define B 4
#define L 512
#define D 128
#define TILE_I 8
#define JCH 128
#define THREADS_A 512

// scratch for q and k projections (allocation-free rule -> __device__ globals)
__device__ float g_q[B * L * D];
__device__ float g_k[B * L * D];

// ---------------------------------------------------------------------------
// Kernel 1: q = x @ Wq^T + bq ; k = x @ Wk^T + bk
// grid = B*L/8 blocks, 128 threads; thread e computes q[r,e],k[r,e] for 8 rows.
// ---------------------------------------------------------------------------
__global__ __launch_bounds__(128) void qk_kernel(
    const float* __restrict__ x,
    const float* __restrict__ Wq, const float* __restrict__ bq,
    const float* __restrict__ Wk, const float* __restrict__ bk)
{
    const int r0 = blockIdx.x * 8;       // first row (b*L + l)
    const int e  = threadIdx.x;          // 0..127 output feature

    __shared__ float xs[8 * D];
    for (int idx = e; idx < 8 * D; idx += 128) xs[idx] = x[r0 * D + idx];
    __syncthreads();

    const float4* wq4 = reinterpret_cast<const float4*>(Wq + e * D);
    const float4* wk4 = reinterpret_cast<const float4*>(Wk + e * D);
    const float4* xs4 = reinterpret_cast<const float4*>(xs);

    float aq[8], ak[8];
#pragma unroll
    for (int r = 0; r < 8; ++r) { aq[r] = 0.f; ak[r] = 0.f; }

#pragma unroll 4
    for (int d4 = 0; d4 < D / 4; ++d4) {
        float4 a = wq4[d4];
        float4 c = wk4[d4];
#pragma unroll
        for (int r = 0; r < 8; ++r) {
            float4 xv = xs4[r * (D / 4) + d4];
            aq[r] = fmaf(a.x, xv.x, aq[r]); aq[r] = fmaf(a.y, xv.y, aq[r]);
            aq[r] = fmaf(a.z, xv.z, aq[r]); aq[r] = fmaf(a.w, xv.w, aq[r]);
            ak[r] = fmaf(c.x, xv.x, ak[r]); ak[r] = fmaf(c.y, xv.y, ak[r]);
            ak[r] = fmaf(c.z, xv.z, ak[r]); ak[r] = fmaf(c.w, xv.w, ak[r]);
        }
    }
    const float bqe = bq[e], bke = bk[e];
#pragma unroll
    for (int r = 0; r < 8; ++r) {
        g_q[(r0 + r) * D + e] = aq[r] + bqe;
        g_k[(r0 + r) * D + e] = ak[r] + bke;
    }
}

// ---------------------------------------------------------------------------
// Kernel 2: 512 threads = 4 d-groups x 128 j-lanes.
// Group g computes partial scores over d in [32g, 32g+32) for j lane tid&127.
// Groups 0/1 write scA/scB; after a sync groups 2/3 ADD into scA/scB (no
// extra smem). Softmax per-warp over scA+scB (warps 0-7). Epilogue splits j
// four ways; partials combined in reused k_s.
// bw dropped (softmax shift-invariant); mask is a faithful no-op.
// smem = 103.5KB -> 2 CTAs/SM x 16 warps = 32 warps/SM (8/SMSP).
// ---------------------------------------------------------------------------
#define SMEM_FLOATS (TILE_I*D + JCH*129 + D + 2*TILE_I*L + TILE_I)
#define SMEM_BYTES  (SMEM_FLOATS * (int)sizeof(float))

__global__ __launch_bounds__(THREADS_A) void attn_kernel(
    const float* __restrict__ x,
    const float* __restrict__ w,
    float* __restrict__ out)
{
    extern __shared__ float smem[];
    float* q_s   = smem;                        // 1024
    float* k_s   = q_s + TILE_I * D;            // 16512 (pad 129)
    float* w_s   = k_s + JCH * 129;             // 128
    float* scA   = w_s + D;                     // 4096
    float* scB   = scA + TILE_I * L;            // 4096
    float* s_inv = scB + TILE_I * L;            // 8

    const int b   = blockIdx.x >> 6;
    const int i0  = (blockIdx.x & 63) * TILE_I;
    const int tid = threadIdx.x;
    const int g   = tid >> 7;                   // d-group 0..3
    const int jl  = tid & 127;                  // j lane

    // load q tile + w (visibility guaranteed by the staging sync below)
    for (int idx = tid; idx < TILE_I * D; idx += THREADS_A)
        q_s[idx] = g_q[(b * L + i0) * D + idx];
    if (tid < D) w_s[tid] = w[tid];

    float* scg = (g & 1) ? scB : scA;
    const int d0 = g * 32;

    // ---- main loop: 4 chunks of 128 j ----
    for (int jc = 0; jc < L / JCH; ++jc) {
        __syncthreads();   // k_s reuse across chunks (+ q_s/w_s on jc=0)
        // stage k chunk: coalesced loads, conflict-free stores
        // (bank = (jj*129 + dd) % 32 = (jj + lane) % 32 -> all distinct)
        {
            const float* kg = g_k + (b * L + jc * JCH) * D;
            for (int idx = tid; idx < JCH * D; idx += THREADS_A) {
                int jj = idx >> 7, dd = idx & 127;
                k_s[jj * 129 + dd] = kg[idx];
            }
        }
        __syncthreads();

        float acc[TILE_I];
#pragma unroll
        for (int i = 0; i < TILE_I; ++i) acc[i] = 0.f;

        const float* krow = &k_s[jl * 129];
#pragma unroll 4
        for (int dz = 0; dz < 32; ++dz) {
            const int d = d0 + dz;
            float kv = krow[d];
            float wd = w_s[d];
#pragma unroll
            for (int i = 0; i < TILE_I; ++i) {
                float t = q_s[i * D + d] + kv;
                float th;
                asm("tanh.approx.f32 %0, %1;" : "=f"(th) : "f"(t));
                acc[i] = fmaf(wd, th, acc[i]);
            }
        }
        if (g < 2) {
#pragma unroll
            for (int i = 0; i < TILE_I; ++i) scg[i * L + jc * JCH + jl] = acc[i];
        }
        __syncthreads();
        if (g >= 2) {
#pragma unroll
            for (int i = 0; i < TILE_I; ++i) scg[i * L + jc * JCH + jl] += acc[i];
        }
    }
    __syncthreads();

    // ---- per-warp softmax: warp wi (0..7) owns row i=wi ----
    {
        const int wi   = tid >> 5;
        const int lane = tid & 31;
        if (wi < TILE_I) {
            float m = -1e30f;
            for (int jj = lane; jj < L; jj += 32)
                m = fmaxf(m, scA[wi * L + jj] + scB[wi * L + jj]);
#pragma unroll
            for (int o = 16; o; o >>= 1) m = fmaxf(m, __shfl_xor_sync(0xffffffffu, m, o));
            float s = 0.f;
            for (int jj = lane; jj < L; jj += 32) {
                float e = __expf(scA[wi * L + jj] + scB[wi * L + jj] - m);
                scA[wi * L + jj] = e;
                s += e;
            }
#pragma unroll
            for (int o = 16; o; o >>= 1) s += __shfl_xor_sync(0xffffffffu, s, o);
            if (lane == 0) s_inv[wi] = 1.0f / s;
        }
    }
    __syncthreads();

    // ---- epilogue: group g sums its 128-j quarter; combine via smem ----
    float o[TILE_I];
#pragma unroll
    for (int i = 0; i < TILE_I; ++i) o[i] = 0.f;

    const float* xb = x + b * L * D;
    const int j0 = g * 128;
#pragma unroll 4
    for (int j = j0; j < j0 + 128; ++j) {
        float xv = xb[j * D + jl];
#pragma unroll
        for (int i = 0; i < TILE_I; ++i)
            o[i] = fmaf(scA[i * L + j], xv, o[i]);
    }

    float* op = k_s;   // reuse k_s: [3][TILE_I][128]
    if (g > 0) {
#pragma unroll
        for (int i = 0; i < TILE_I; ++i)
            op[((g - 1) * TILE_I + i) * 128 + jl] = o[i];
    }
    __syncthreads();
    if (g == 0) {
#pragma unroll
        for (int i = 0; i < TILE_I; ++i) {
            float v = o[i] + op[(0 * TILE_I + i) * 128 + jl]
                          + op[(1 * TILE_I + i) * 128 + jl]
                          + op[(2 * TILE_I + i) * 128 + jl];
            out[(b * L + i0 + i) * D + jl] = v * s_inv[i];
        }
    }
}

// ---------------------------------------------------------------------------
extern "C" void kernel_launch(void* const* d_in, const int* in_sizes, int n_in,
                              void* d_out, int out_size)
{
    const float* x  = (const float*)d_in[0];
    // d_in[1] = mask (bool, faithfully unused by reference)
    const float* Wq = (const float*)d_in[2];
    const float* bq = (const float*)d_in[3];
    const float* Wk = (const float*)d_in[4];
    const float* bk = (const float*)d_in[5];
    const float* w  = (const float*)d_in[6];
    // d_in[7] = bw: constant shift before softmax -> no effect on output
    float* out = (float*)d_out;

    cudaFuncSetAttribute(attn_kernel, cudaFuncAttributeMaxDynamicSharedMemorySize,
                         SMEM_BYTES);

    qk_kernel<<<B * L / 8, 128>>>(x, Wq, bq, Wk, bk);
    attn_kernel<<<B * (L / TILE_I), THREADS_A, SMEM_BYTES>>>(x, w, out);
}